// round 2
// baseline (speedup 1.0000x reference)
#include <cuda_runtime.h>
#include <cuda_bf16.h>
#include <cstdint>

// ---------------------------------------------------------------------------
// OuterProductMean (AlphaFold-style), shapes fixed by the problem instance:
//   msa [1,128,256,256] -> LN -> A,B [128,256,32]
//   G[(i,c),(j,d)] = sum_s A[s,i,c] B[s,j,d]        (GEMM1: 8192x8192x128)
//   out[i,j,z]     = (1/128) * G_flat @ W_out + b_out (GEMM2: 65536x128x1024)
// Precision: TF32 mma.sync with fp32 accumulation (rel_err budget ~5e-4).
// ---------------------------------------------------------------------------

#define S_DIM   128
#define NRES    256
#define CS_DIM  256
#define C_DIM   32
#define CZ_DIM  128
#define M1      (NRES * C_DIM)      // 8192
#define K2      (C_DIM * C_DIM)     // 1024

// Scratch (device globals: allocation-free contract)
__device__ float d_A[S_DIM * M1];               // [s][i*32+c], tf32-rounded
__device__ float d_B[S_DIM * M1];               // [s][j*32+d], tf32-rounded
__device__ float d_G[(size_t)M1 * M1];          // [(i,c)][(j,d)] fp32

__device__ __forceinline__ float tf32r(float x) {
    uint32_t u;
    asm("cvt.rna.tf32.f32 %0, %1;" : "=r"(u) : "f"(x));
    return __uint_as_float(u);
}

__device__ __forceinline__ void mma_tf32(float* c, const uint32_t* a, const uint32_t* b) {
    asm volatile(
        "mma.sync.aligned.m16n8k8.row.col.f32.tf32.tf32.f32 "
        "{%0,%1,%2,%3}, {%4,%5,%6,%7}, {%8,%9}, {%0,%1,%2,%3};\n"
        : "+f"(c[0]), "+f"(c[1]), "+f"(c[2]), "+f"(c[3])
        : "r"(a[0]), "r"(a[1]), "r"(a[2]), "r"(a[3]),
          "r"(b[0]), "r"(b[1]));
}

// ---------------------------------------------------------------------------
// Kernel 1: LayerNorm + left/right projections. One block per (s,i) row.
// 256 threads: phase 1 all threads LN; phase 2: 8 warps = {A,B} x 4 k-parts,
// lane = output channel c.
// ---------------------------------------------------------------------------
__global__ __launch_bounds__(256) void ln_proj_kernel(
    const float* __restrict__ msa,
    const float* __restrict__ gamma, const float* __restrict__ beta,
    const float* __restrict__ Wl, const float* __restrict__ bl,
    const float* __restrict__ Wr, const float* __restrict__ br)
{
    const int row = blockIdx.x;            // row = s*256 + i
    const int t = threadIdx.x;
    const int lane = t & 31, wid = t >> 5;

    __shared__ float xn[CS_DIM];
    __shared__ float rs1[8], rs2[8];
    __shared__ float stats[2];
    __shared__ float partials[2][4][32];

    const float v = msa[(size_t)row * CS_DIM + t];
    float s1 = v, s2 = v * v;
    #pragma unroll
    for (int o = 16; o; o >>= 1) {
        s1 += __shfl_xor_sync(0xFFFFFFFFu, s1, o);
        s2 += __shfl_xor_sync(0xFFFFFFFFu, s2, o);
    }
    if (lane == 0) { rs1[wid] = s1; rs2[wid] = s2; }
    __syncthreads();
    if (t == 0) {
        float a = 0.f, b = 0.f;
        #pragma unroll
        for (int w = 0; w < 8; w++) { a += rs1[w]; b += rs2[w]; }
        const float mu = a * (1.0f / CS_DIM);
        const float var = b * (1.0f / CS_DIM) - mu * mu;
        stats[0] = mu;
        stats[1] = rsqrtf(var + 1e-5f);
    }
    __syncthreads();
    xn[t] = (v - stats[0]) * stats[1] * gamma[t] + beta[t];
    __syncthreads();

    // phase 2: t -> (c = lane, part = warp&3, matB = warp>>2)
    const int c = lane;
    const int part = wid & 3;
    const int matB = wid >> 2;              // 0 = A (left), 1 = B (right)
    const float* __restrict__ W = matB ? Wr : Wl;
    float acc = 0.f;
    const int k0 = part * 64;
    #pragma unroll 8
    for (int k = k0; k < k0 + 64; k++)
        acc += xn[k] * W[k * C_DIM + c];
    partials[matB][part][c] = acc;
    __syncthreads();

    if (part == 0) {
        float sum = partials[matB][0][c] + partials[matB][1][c]
                  + partials[matB][2][c] + partials[matB][3][c];
        sum += matB ? br[c] : bl[c];
        const int s = row >> 8;             // NRES = 256
        const int i = row & 255;
        float* __restrict__ dst = matB ? d_B : d_A;
        dst[(size_t)s * M1 + i * C_DIM + c] = tf32r(sum);
    }
}

// ---------------------------------------------------------------------------
// Kernel 2: GEMM1  G = A^T(K-major) x B(K-major), M=N=8192, K=128, tf32 MMA.
// CTA tile 128x128, 8 warps (4x2), warp tile 32x64, BK=32.
// ---------------------------------------------------------------------------
__global__ __launch_bounds__(256) void gemm1_kernel()
{
    __shared__ __align__(16) float As[32][136];   // [k][m], pad 8 -> conflict-free frags
    __shared__ __align__(16) float Bs[32][136];   // [k][n]

    const int t = threadIdx.x;
    const int lane = t & 31, wid = t >> 5;
    const int warpM = wid & 3, warpN = wid >> 2;
    const int bm = blockIdx.y, bn = blockIdx.x;
    const int ctid = lane & 3, g = lane >> 2;

    float acc[2][8][4] = {};

    for (int kt = 0; kt < 4; kt++) {
        #pragma unroll
        for (int l = 0; l < 4; l++) {
            const int idx = t + l * 256;
            const int r = idx >> 5, c4 = idx & 31;
            const size_t goff = (size_t)(kt * 32 + r) * M1;
            const float4 a4 = *(const float4*)&d_A[goff + bm * 128 + c4 * 4];
            *(float4*)&As[r][c4 * 4] = a4;
            const float4 b4 = *(const float4*)&d_B[goff + bn * 128 + c4 * 4];
            *(float4*)&Bs[r][c4 * 4] = b4;
        }
        __syncthreads();

        #pragma unroll
        for (int k8 = 0; k8 < 4; k8++) {
            const int kb = k8 * 8;
            uint32_t a[2][4], b[8][2];
            #pragma unroll
            for (int mi = 0; mi < 2; mi++) {
                const int m = warpM * 32 + mi * 16 + g;
                a[mi][0] = __float_as_uint(As[kb + ctid][m]);
                a[mi][1] = __float_as_uint(As[kb + ctid][m + 8]);
                a[mi][2] = __float_as_uint(As[kb + ctid + 4][m]);
                a[mi][3] = __float_as_uint(As[kb + ctid + 4][m + 8]);
            }
            #pragma unroll
            for (int ni = 0; ni < 8; ni++) {
                const int n = warpN * 64 + ni * 8 + g;
                b[ni][0] = __float_as_uint(Bs[kb + ctid][n]);
                b[ni][1] = __float_as_uint(Bs[kb + ctid + 4][n]);
            }
            #pragma unroll
            for (int mi = 0; mi < 2; mi++)
                #pragma unroll
                for (int ni = 0; ni < 8; ni++)
                    mma_tf32(acc[mi][ni], a[mi], b[ni]);
        }
        __syncthreads();
    }

    // epilogue: fp32 G to scratch
    #pragma unroll
    for (int mi = 0; mi < 2; mi++) {
        const int r0 = bm * 128 + warpM * 32 + mi * 16 + g;
        #pragma unroll
        for (int ni = 0; ni < 8; ni++) {
            const int col = bn * 128 + warpN * 64 + ni * 8 + ctid * 2;
            *(float2*)&d_G[(size_t)r0 * M1 + col] =
                make_float2(acc[mi][ni][0], acc[mi][ni][1]);
            *(float2*)&d_G[(size_t)(r0 + 8) * M1 + col] =
                make_float2(acc[mi][ni][2], acc[mi][ni][3]);
        }
    }
}

// ---------------------------------------------------------------------------
// Kernel 3: GEMM2  out = (G_flat/128) @ W_out + b_out.
// M=65536 pairs (p=i*256+j), K=1024 (cd=c*32+d), N=128. CTA tile 128x128,
// BK=32 (exactly one c per K-tile since tiles are 32-aligned).
// A gathered from d_G: A2[p][cd] = G[(i*32+c)*8192 + j*32+d].
// ---------------------------------------------------------------------------
__global__ __launch_bounds__(256) void gemm2_kernel(
    const float* __restrict__ W_out, const float* __restrict__ b_out,
    float* __restrict__ out)
{
    __shared__ __align__(16) float As[128][36];   // [p][k], pad 4 -> conflict-free frags
    __shared__ __align__(16) float Bs[32][136];   // [k][z]

    const int t = threadIdx.x;
    const int lane = t & 31, wid = t >> 5;
    const int warpM = wid & 3, warpN = wid >> 2;
    const int bm = blockIdx.x;                    // 512 blocks of 128 pairs
    const int ctid = lane & 3, g = lane >> 2;

    float acc[2][8][4] = {};

    for (int kt = 0; kt < 32; kt++) {             // c = kt
        // A tile: 128 pairs x 32 d-values
        for (int idx = t; idx < 1024; idx += 256) {
            const int p = idx >> 3, q = idx & 7;
            const int gp = bm * 128 + p;
            const int i = gp >> 8, j = gp & 255;
            const float4 v = *(const float4*)
                &d_G[(size_t)(i * C_DIM + kt) * M1 + j * C_DIM + q * 4];
            float4 r;
            r.x = tf32r(v.x); r.y = tf32r(v.y); r.z = tf32r(v.z); r.w = tf32r(v.w);
            *(float4*)&As[p][q * 4] = r;
        }
        // B tile: W_out rows kt*32..kt*32+31
        #pragma unroll
        for (int l = 0; l < 4; l++) {
            const int idx = t + l * 256;
            const int r = idx >> 5, c4 = idx & 31;
            const float4 w = *(const float4*)&W_out[(kt * 32 + r) * CZ_DIM + c4 * 4];
            float4 rw;
            rw.x = tf32r(w.x); rw.y = tf32r(w.y); rw.z = tf32r(w.z); rw.w = tf32r(w.w);
            *(float4*)&Bs[r][c4 * 4] = rw;
        }
        __syncthreads();

        #pragma unroll
        for (int k8 = 0; k8 < 4; k8++) {
            const int kb = k8 * 8;
            uint32_t a[2][4], b[8][2];
            #pragma unroll
            for (int mi = 0; mi < 2; mi++) {
                const int m = warpM * 32 + mi * 16 + g;
                a[mi][0] = __float_as_uint(As[m][kb + ctid]);
                a[mi][1] = __float_as_uint(As[m + 8][kb + ctid]);
                a[mi][2] = __float_as_uint(As[m][kb + ctid + 4]);
                a[mi][3] = __float_as_uint(As[m + 8][kb + ctid + 4]);
            }
            #pragma unroll
            for (int ni = 0; ni < 8; ni++) {
                const int n = warpN * 64 + ni * 8 + g;
                b[ni][0] = __float_as_uint(Bs[kb + ctid][n]);
                b[ni][1] = __float_as_uint(Bs[kb + ctid + 4][n]);
            }
            #pragma unroll
            for (int mi = 0; mi < 2; mi++)
                #pragma unroll
                for (int ni = 0; ni < 8; ni++)
                    mma_tf32(acc[mi][ni], a[mi], b[ni]);
        }
        __syncthreads();
    }

    // epilogue: mean (1/s) + bias
    const float inv_s = 1.0f / (float)S_DIM;
    #pragma unroll
    for (int mi = 0; mi < 2; mi++) {
        const int p0 = bm * 128 + warpM * 32 + mi * 16 + g;
        #pragma unroll
        for (int ni = 0; ni < 8; ni++) {
            const int z = warpN * 64 + ni * 8 + ctid * 2;
            const float bz0 = b_out[z], bz1 = b_out[z + 1];
            *(float2*)&out[(size_t)p0 * CZ_DIM + z] =
                make_float2(acc[mi][ni][0] * inv_s + bz0,
                            acc[mi][ni][1] * inv_s + bz1);
            *(float2*)&out[(size_t)(p0 + 8) * CZ_DIM + z] =
                make_float2(acc[mi][ni][2] * inv_s + bz0,
                            acc[mi][ni][3] * inv_s + bz1);
        }
    }
}

// ---------------------------------------------------------------------------
extern "C" void kernel_launch(void* const* d_in, const int* in_sizes, int n_in,
                              void* d_out, int out_size)
{
    const float* msa   = (const float*)d_in[0];
    const float* gam   = (const float*)d_in[1];
    const float* bet   = (const float*)d_in[2];
    const float* Wl    = (const float*)d_in[3];
    const float* bl    = (const float*)d_in[4];
    const float* Wr    = (const float*)d_in[5];
    const float* br    = (const float*)d_in[6];
    const float* Wout  = (const float*)d_in[7];
    const float* bout  = (const float*)d_in[8];
    float* out = (float*)d_out;

    ln_proj_kernel<<<S_DIM * NRES, 256>>>(msa, gam, bet, Wl, bl, Wr, br);
    gemm1_kernel<<<dim3(M1 / 128, M1 / 128), 256>>>();
    gemm2_kernel<<<(NRES * NRES) / 128, 256>>>(Wout, bout, out);
}

// round 3
// speedup vs baseline: 1.7947x; 1.7947x over previous
#include <cuda_runtime.h>
#include <cuda_bf16.h>
#include <cstdint>

// ---------------------------------------------------------------------------
// OuterProductMean: msa[1,128,256,256] -> LN -> A,B[128,256,32]
//   G = A^T B (8192x8192x128), out = (G/128) @ W_out + b_out (65536x128x1024)
// TF32 HMMA everywhere, fp32 accum. cp.async 3-stage pipelines.
// ---------------------------------------------------------------------------

#define S_DIM   128
#define NRES    256
#define CS_DIM  256
#define C_DIM   32
#define CZ_DIM  128
#define M1      (NRES * C_DIM)      // 8192

__device__ float d_A[S_DIM * M1];      // [s][i*32+c], tf32-rounded
__device__ float d_B[S_DIM * M1];      // [s][j*32+d], tf32-rounded
__device__ float d_G[(size_t)M1 * M1]; // fp32

__device__ __forceinline__ float tf32r(float x) {
    uint32_t u;
    asm("cvt.rna.tf32.f32 %0, %1;" : "=r"(u) : "f"(x));
    return __uint_as_float(u);
}
__device__ __forceinline__ uint32_t f2tf(float x) {
    uint32_t u;
    asm("cvt.rna.tf32.f32 %0, %1;" : "=r"(u) : "f"(x));
    return u;
}
__device__ __forceinline__ void mma_tf32(float* c, const uint32_t* a, const uint32_t* b) {
    asm volatile(
        "mma.sync.aligned.m16n8k8.row.col.f32.tf32.tf32.f32 "
        "{%0,%1,%2,%3}, {%4,%5,%6,%7}, {%8,%9}, {%0,%1,%2,%3};\n"
        : "+f"(c[0]), "+f"(c[1]), "+f"(c[2]), "+f"(c[3])
        : "r"(a[0]), "r"(a[1]), "r"(a[2]), "r"(a[3]), "r"(b[0]), "r"(b[1]));
}
__device__ __forceinline__ void cp16(uint32_t s, const void* g) {
    asm volatile("cp.async.cg.shared.global [%0], [%1], 16;" :: "r"(s), "l"(g));
}
__device__ __forceinline__ void cp_commit() {
    asm volatile("cp.async.commit_group;");
}
template <int N> __device__ __forceinline__ void cp_wait() {
    asm volatile("cp.async.wait_group %0;" :: "n"(N));
}

// ---------------------------------------------------------------------------
// Kernel 1: fused LN + both projections as tf32 HMMA GEMM.
// CTA: 64 rows x 64 outputs (Wl||Wr), K=256. 8 warps: 2(M)x4(N), warp 32x16.
// smem: xn[64][260] (fp32 -> tf32 in place), Wc[256][68], gamma/beta[512].
// ---------------------------------------------------------------------------
#define K1_XN_PITCH 260
#define K1_W_PITCH  68
#define K1_SMEM_FLOATS (64 * K1_XN_PITCH + 256 * K1_W_PITCH + 512)

__global__ __launch_bounds__(256) void ln_proj_kernel(
    const float* __restrict__ msa,
    const float* __restrict__ gamma, const float* __restrict__ beta,
    const float* __restrict__ Wl, const float* __restrict__ bl,
    const float* __restrict__ Wr, const float* __restrict__ br)
{
    extern __shared__ float sm[];
    float* xn = sm;                              // [64][260]
    float* Wc = sm + 64 * K1_XN_PITCH;           // [256][68], cols 0..63 used
    float* gb = Wc + 256 * K1_W_PITCH;           // gamma[0..255], beta[256..511]

    const int t = threadIdx.x, lane = t & 31, wid = t >> 5;
    const int R0 = blockIdx.x * 64;              // global row base (s*256+i)

    // ---- async staging: msa rows, W (both), gamma/beta ----
    {
        const uint32_t xnb = (uint32_t)__cvta_generic_to_shared(xn);
        #pragma unroll
        for (int it = 0; it < 16; it++) {
            const int idx = t + it * 256;        // 4096 float4s
            const int r = idx >> 6, c4 = idx & 63;
            cp16(xnb + (uint32_t)(r * K1_XN_PITCH + c4 * 4) * 4,
                 &msa[(size_t)(R0 + r) * CS_DIM + c4 * 4]);
        }
        const uint32_t wb = (uint32_t)__cvta_generic_to_shared(Wc);
        #pragma unroll
        for (int it = 0; it < 16; it++) {
            const int idx = t + it * 256;        // 4096 float4s
            const int r = idx >> 4, q = idx & 15;
            const float* src = (q < 8) ? &Wl[r * C_DIM + q * 4]
                                       : &Wr[r * C_DIM + (q - 8) * 4];
            const int col = (q < 8) ? q * 4 : 32 + (q - 8) * 4;
            cp16(wb + (uint32_t)(r * K1_W_PITCH + col) * 4, src);
        }
        const uint32_t gbb = (uint32_t)__cvta_generic_to_shared(gb);
        if (t < 128) {
            const float* src = (t < 64) ? &gamma[t * 4] : &beta[(t - 64) * 4];
            cp16(gbb + t * 16, src);
        }
        cp_commit();
        cp_wait<0>();
    }
    __syncthreads();

    // ---- LayerNorm in place (each warp owns 8 rows), write tf32 ----
    #pragma unroll
    for (int rr = 0; rr < 8; rr++) {
        const int r = wid * 8 + rr;
        float* row = &xn[r * K1_XN_PITCH];
        float4 v0 = *(float4*)&row[lane * 8];
        float4 v1 = *(float4*)&row[lane * 8 + 4];
        float s1 = v0.x + v0.y + v0.z + v0.w + v1.x + v1.y + v1.z + v1.w;
        float s2 = v0.x*v0.x + v0.y*v0.y + v0.z*v0.z + v0.w*v0.w
                 + v1.x*v1.x + v1.y*v1.y + v1.z*v1.z + v1.w*v1.w;
        #pragma unroll
        for (int o = 16; o; o >>= 1) {
            s1 += __shfl_xor_sync(0xFFFFFFFFu, s1, o);
            s2 += __shfl_xor_sync(0xFFFFFFFFu, s2, o);
        }
        const float mu = s1 * (1.0f / CS_DIM);
        const float rstd = rsqrtf(s2 * (1.0f / CS_DIM) - mu * mu + 1e-5f);
        const float4 g0 = *(float4*)&gb[lane * 8];
        const float4 g1 = *(float4*)&gb[lane * 8 + 4];
        const float4 b0 = *(float4*)&gb[256 + lane * 8];
        const float4 b1 = *(float4*)&gb[256 + lane * 8 + 4];
        float4 o0, o1;
        o0.x = tf32r((v0.x - mu) * rstd * g0.x + b0.x);
        o0.y = tf32r((v0.y - mu) * rstd * g0.y + b0.y);
        o0.z = tf32r((v0.z - mu) * rstd * g0.z + b0.z);
        o0.w = tf32r((v0.w - mu) * rstd * g0.w + b0.w);
        o1.x = tf32r((v1.x - mu) * rstd * g1.x + b1.x);
        o1.y = tf32r((v1.y - mu) * rstd * g1.y + b1.y);
        o1.z = tf32r((v1.z - mu) * rstd * g1.z + b1.z);
        o1.w = tf32r((v1.w - mu) * rstd * g1.w + b1.w);
        *(float4*)&row[lane * 8] = o0;
        *(float4*)&row[lane * 8 + 4] = o1;
    }
    __syncthreads();

    // ---- GEMM: [64 x 256] x [256 x 64] ----
    const int warpM = wid & 1, warpN = wid >> 1;
    const int ctid = lane & 3, g = lane >> 2;
    float acc[2][2][4] = {};

    #pragma unroll 8
    for (int k8 = 0; k8 < 32; k8++) {
        const int kb = k8 * 8;
        uint32_t a[2][4], b[2][2];
        #pragma unroll
        for (int mi = 0; mi < 2; mi++) {
            const int m = warpM * 32 + mi * 16 + g;
            a[mi][0] = __float_as_uint(xn[m * K1_XN_PITCH + kb + ctid]);
            a[mi][1] = __float_as_uint(xn[(m + 8) * K1_XN_PITCH + kb + ctid]);
            a[mi][2] = __float_as_uint(xn[m * K1_XN_PITCH + kb + ctid + 4]);
            a[mi][3] = __float_as_uint(xn[(m + 8) * K1_XN_PITCH + kb + ctid + 4]);
        }
        #pragma unroll
        for (int ni = 0; ni < 2; ni++) {
            const int n = warpN * 16 + ni * 8 + g;
            b[ni][0] = f2tf(Wc[(kb + ctid) * K1_W_PITCH + n]);
            b[ni][1] = f2tf(Wc[(kb + ctid + 4) * K1_W_PITCH + n]);
        }
        #pragma unroll
        for (int mi = 0; mi < 2; mi++)
            #pragma unroll
            for (int ni = 0; ni < 2; ni++)
                mma_tf32(acc[mi][ni], a[mi], b[ni]);
    }

    // ---- epilogue: bias, tf32 round, scatter to d_A/d_B ----
    #pragma unroll
    for (int mi = 0; mi < 2; mi++) {
        #pragma unroll
        for (int ni = 0; ni < 2; ni++) {
            const int n = warpN * 16 + ni * 8 + ctid * 2;
            #pragma unroll
            for (int e = 0; e < 4; e++) {
                const int m = warpM * 32 + mi * 16 + g + (e >= 2 ? 8 : 0);
                const int nn = n + (e & 1);
                const int row = R0 + m;
                const int s = row >> 8, i = row & 255;
                float v = acc[mi][ni][e];
                if (nn < 32)
                    d_A[(size_t)s * M1 + i * C_DIM + nn] = tf32r(v + __ldg(&bl[nn]));
                else
                    d_B[(size_t)s * M1 + i * C_DIM + (nn - 32)] = tf32r(v + __ldg(&br[nn - 32]));
            }
        }
    }
}

// ---------------------------------------------------------------------------
// Kernel 2: GEMM1 G = A^T B, 8192x8192x128. CTA 128x128, BK=32, 3-stage
// cp.async. 8 warps 4x2, warp tile 32x64.
// ---------------------------------------------------------------------------
#define G1_STAGE (32 * 136)
#define K2_SMEM_FLOATS (2 * 3 * G1_STAGE)

__global__ __launch_bounds__(256, 2) void gemm1_kernel()
{
    extern __shared__ float sm[];
    float* sA = sm;                    // [3][32][136]
    float* sB = sm + 3 * G1_STAGE;
    const uint32_t sAb = (uint32_t)__cvta_generic_to_shared(sA);
    const uint32_t sBb = (uint32_t)__cvta_generic_to_shared(sB);

    const int t = threadIdx.x, lane = t & 31, wid = t >> 5;
    const int warpM = wid & 3, warpN = wid >> 2;
    const int bm = blockIdx.y, bn = blockIdx.x;
    const int ctid = lane & 3, g = lane >> 2;

    auto load_stage = [&](int st, int kt) {
        #pragma unroll
        for (int it = 0; it < 4; it++) {
            const int idx = t + it * 256;          // 1024 float4 each matrix
            const int r = idx >> 5, c4 = idx & 31;
            const size_t go = (size_t)(kt * 32 + r) * M1;
            const uint32_t so = (uint32_t)(st * G1_STAGE + r * 136 + c4 * 4) * 4;
            cp16(sAb + so, &d_A[go + bm * 128 + c4 * 4]);
            cp16(sBb + so, &d_B[go + bn * 128 + c4 * 4]);
        }
    };

    float acc[2][8][4] = {};

    load_stage(0, 0); cp_commit();
    load_stage(1, 1); cp_commit();

    for (int kt = 0; kt < 4; kt++) {
        if (kt + 2 < 4) load_stage((kt + 2) % 3, kt + 2);
        cp_commit();
        cp_wait<2>();
        __syncthreads();

        const float* A = sA + (kt % 3) * G1_STAGE;
        const float* B = sB + (kt % 3) * G1_STAGE;
        #pragma unroll
        for (int k8 = 0; k8 < 4; k8++) {
            const int kb = k8 * 8;
            uint32_t a[2][4], b[8][2];
            #pragma unroll
            for (int mi = 0; mi < 2; mi++) {
                const int m = warpM * 32 + mi * 16 + g;
                a[mi][0] = __float_as_uint(A[(kb + ctid) * 136 + m]);
                a[mi][1] = __float_as_uint(A[(kb + ctid) * 136 + m + 8]);
                a[mi][2] = __float_as_uint(A[(kb + ctid + 4) * 136 + m]);
                a[mi][3] = __float_as_uint(A[(kb + ctid + 4) * 136 + m + 8]);
            }
            #pragma unroll
            for (int ni = 0; ni < 8; ni++) {
                const int n = warpN * 64 + ni * 8 + g;
                b[ni][0] = __float_as_uint(B[(kb + ctid) * 136 + n]);
                b[ni][1] = __float_as_uint(B[(kb + ctid + 4) * 136 + n]);
            }
            #pragma unroll
            for (int mi = 0; mi < 2; mi++)
                #pragma unroll
                for (int ni = 0; ni < 8; ni++)
                    mma_tf32(acc[mi][ni], a[mi], b[ni]);
        }
        __syncthreads();
    }

    #pragma unroll
    for (int mi = 0; mi < 2; mi++) {
        const int r0 = bm * 128 + warpM * 32 + mi * 16 + g;
        #pragma unroll
        for (int ni = 0; ni < 8; ni++) {
            const int col = bn * 128 + warpN * 64 + ni * 8 + ctid * 2;
            *(float2*)&d_G[(size_t)r0 * M1 + col] =
                make_float2(acc[mi][ni][0], acc[mi][ni][1]);
            *(float2*)&d_G[(size_t)(r0 + 8) * M1 + col] =
                make_float2(acc[mi][ni][2], acc[mi][ni][3]);
        }
    }
}

// ---------------------------------------------------------------------------
// Kernel 3: GEMM2 out = (G/128) @ W_out + b_out. M=65536, K=1024, N=128.
// CTA 128x128, BK=32, 3-stage cp.async, tf32 cvt at frag-load time.
// ---------------------------------------------------------------------------
#define G2_A_STAGE (128 * 36)
#define G2_B_STAGE (32 * 136)
#define K3_SMEM_FLOATS (3 * G2_A_STAGE + 3 * G2_B_STAGE)

__global__ __launch_bounds__(256, 2) void gemm2_kernel(
    const float* __restrict__ W_out, const float* __restrict__ b_out,
    float* __restrict__ out)
{
    extern __shared__ float sm[];
    float* sA = sm;                       // [3][128][36]
    float* sB = sm + 3 * G2_A_STAGE;      // [3][32][136]
    const uint32_t sAb = (uint32_t)__cvta_generic_to_shared(sA);
    const uint32_t sBb = (uint32_t)__cvta_generic_to_shared(sB);

    const int t = threadIdx.x, lane = t & 31, wid = t >> 5;
    const int warpM = wid & 3, warpN = wid >> 2;
    const int bm = blockIdx.x;
    const int ctid = lane & 3, g = lane >> 2;

    auto load_stage = [&](int st, int kt) {
        #pragma unroll
        for (int it = 0; it < 4; it++) {
            const int idx = t + it * 256;               // 1024 each
            const int p = idx >> 3, q = idx & 7;
            const int gp = bm * 128 + p, i = gp >> 8, j = gp & 255;
            cp16(sAb + (uint32_t)(st * G2_A_STAGE + p * 36 + q * 4) * 4,
                 &d_G[(size_t)(i * C_DIM + kt) * M1 + j * C_DIM + q * 4]);
            const int r = idx >> 5, c4 = idx & 31;
            cp16(sBb + (uint32_t)(st * G2_B_STAGE + r * 136 + c4 * 4) * 4,
                 &W_out[(kt * 32 + r) * CZ_DIM + c4 * 4]);
        }
    };

    float acc[2][8][4] = {};

    load_stage(0, 0); cp_commit();
    load_stage(1, 1); cp_commit();

    for (int kt = 0; kt < 32; kt++) {
        if (kt + 2 < 32) load_stage((kt + 2) % 3, kt + 2);
        cp_commit();
        cp_wait<2>();
        __syncthreads();

        const float* A = sA + (kt % 3) * G2_A_STAGE;
        const float* B = sB + (kt % 3) * G2_B_STAGE;
        #pragma unroll
        for (int k8 = 0; k8 < 4; k8++) {
            const int kb = k8 * 8;
            uint32_t a[2][4], b[8][2];
            #pragma unroll
            for (int mi = 0; mi < 2; mi++) {
                const int m = warpM * 32 + mi * 16 + g;
                a[mi][0] = f2tf(A[m * 36 + kb + ctid]);
                a[mi][1] = f2tf(A[(m + 8) * 36 + kb + ctid]);
                a[mi][2] = f2tf(A[m * 36 + kb + ctid + 4]);
                a[mi][3] = f2tf(A[(m + 8) * 36 + kb + ctid + 4]);
            }
            #pragma unroll
            for (int ni = 0; ni < 8; ni++) {
                const int n = warpN * 64 + ni * 8 + g;
                b[ni][0] = f2tf(B[(kb + ctid) * 136 + n]);
                b[ni][1] = f2tf(B[(kb + ctid + 4) * 136 + n]);
            }
            #pragma unroll
            for (int mi = 0; mi < 2; mi++)
                #pragma unroll
                for (int ni = 0; ni < 8; ni++)
                    mma_tf32(acc[mi][ni], a[mi], b[ni]);
        }
        __syncthreads();
    }

    const float inv_s = 1.0f / (float)S_DIM;
    #pragma unroll
    for (int mi = 0; mi < 2; mi++) {
        const int p0 = bm * 128 + warpM * 32 + mi * 16 + g;
        #pragma unroll
        for (int ni = 0; ni < 8; ni++) {
            const int z = warpN * 64 + ni * 8 + ctid * 2;
            const float bz0 = b_out[z], bz1 = b_out[z + 1];
            *(float2*)&out[(size_t)p0 * CZ_DIM + z] =
                make_float2(acc[mi][ni][0] * inv_s + bz0,
                            acc[mi][ni][1] * inv_s + bz1);
            *(float2*)&out[(size_t)(p0 + 8) * CZ_DIM + z] =
                make_float2(acc[mi][ni][2] * inv_s + bz0,
                            acc[mi][ni][3] * inv_s + bz1);
        }
    }
}

// ---------------------------------------------------------------------------
extern "C" void kernel_launch(void* const* d_in, const int* in_sizes, int n_in,
                              void* d_out, int out_size)
{
    const float* msa  = (const float*)d_in[0];
    const float* gam  = (const float*)d_in[1];
    const float* bet  = (const float*)d_in[2];
    const float* Wl   = (const float*)d_in[3];
    const float* bl   = (const float*)d_in[4];
    const float* Wr   = (const float*)d_in[5];
    const float* br   = (const float*)d_in[6];
    const float* Wout = (const float*)d_in[7];
    const float* bout = (const float*)d_in[8];
    float* out = (float*)d_out;

    cudaFuncSetAttribute(ln_proj_kernel, cudaFuncAttributeMaxDynamicSharedMemorySize,
                         K1_SMEM_FLOATS * 4);
    cudaFuncSetAttribute(gemm1_kernel, cudaFuncAttributeMaxDynamicSharedMemorySize,
                         K2_SMEM_FLOATS * 4);
    cudaFuncSetAttribute(gemm2_kernel, cudaFuncAttributeMaxDynamicSharedMemorySize,
                         K3_SMEM_FLOATS * 4);

    ln_proj_kernel<<<512, 256, K1_SMEM_FLOATS * 4>>>(msa, gam, bet, Wl, bl, Wr, br);
    gemm1_kernel<<<dim3(M1 / 128, M1 / 128), 256, K2_SMEM_FLOATS * 4>>>();
    gemm2_kernel<<<(NRES * NRES) / 128, 256, K3_SMEM_FLOATS * 4>>>(Wout, bout, out);
}